// round 4
// baseline (speedup 1.0000x reference)
#include <cuda_runtime.h>

// EMA over time: y_t = 0.1*y_{t-1} + 0.9*x_t, y_{-1} = 0.
// x [B=16, T=4000, C=512] fp32 -> y same shape.
//
// Decay is 10x per step: W-step warmup rebuilds carry to 0.1^W rel error,
// so T-chunks are independent -> fully parallel streaming kernel.
//
// R3 changes vs R2/R1: the G=8 batch never materialized (regs stayed 32 ->
// ptxas serialized the loads). Fix: __launch_bounds__(128, 8) grants a
// 64-reg budget so a true G=10 float4 load batch stays live (MLP_p1 ~ 10).
// CHUNK back to 50 (R2's best). W=6, streaming stores kept.

static constexpr int B = 16;
static constexpr int T = 4000;
static constexpr int C = 512;
static constexpr int C4 = C / 4;        // 128 float4 lanes per (b,t) row
static constexpr int CHUNK = 50;        // 80 chunks along T -> 1280 CTAs
static constexpr int NCHUNK = T / CHUNK;
static constexpr int W = 6;             // warmup steps; 0.1^6 = 1e-6
static constexpr int G = 10;            // timesteps batched per inner iter

__global__ __launch_bounds__(C4, 8) void ema_kernel(const float4* __restrict__ x,
                                                    float4* __restrict__ y) {
    const int c4 = threadIdx.x;          // 0..127
    const int chunk = blockIdx.x;        // 0..79
    const int b = blockIdx.y;            // 0..15

    const float a = 0.9f;
    const float om = 0.1f;

    const int t0 = chunk * CHUNK;
    const size_t base = (size_t)b * T * C4 + c4;

    float4 acc = make_float4(0.f, 0.f, 0.f, 0.f);

    // Warmup: rebuild carry from up to W steps back (first chunk has none).
    if (t0 >= W) {
        size_t widx = base + (size_t)(t0 - W) * C4;
        float4 v[W];
        #pragma unroll
        for (int t = 0; t < W; ++t) v[t] = x[widx + (size_t)t * C4];
        #pragma unroll
        for (int t = 0; t < W; ++t) {
            acc.x = fmaf(om, acc.x, a * v[t].x);
            acc.y = fmaf(om, acc.y, a * v[t].y);
            acc.z = fmaf(om, acc.z, a * v[t].z);
            acc.w = fmaf(om, acc.w, a * v[t].w);
        }
    }

    // Main chunk: G-wide load batches (all live in regs), serial FMA chain,
    // store each result immediately (STG is issue-only, frees nothing to wait on).
    size_t idx = base + (size_t)t0 * C4;
    for (int g = 0; g < CHUNK / G; ++g) {
        float4 v[G];
        #pragma unroll
        for (int t = 0; t < G; ++t) v[t] = x[idx + (size_t)t * C4];
        #pragma unroll
        for (int t = 0; t < G; ++t) {
            acc.x = fmaf(om, acc.x, a * v[t].x);
            acc.y = fmaf(om, acc.y, a * v[t].y);
            acc.z = fmaf(om, acc.z, a * v[t].z);
            acc.w = fmaf(om, acc.w, a * v[t].w);
            __stcs(&y[idx + (size_t)t * C4], acc);
        }
        idx += (size_t)G * C4;
    }
}

extern "C" void kernel_launch(void* const* d_in, const int* in_sizes, int n_in,
                              void* d_out, int out_size) {
    const float4* x = (const float4*)d_in[0];
    float4* y = (float4*)d_out;
    dim3 grid(NCHUNK, B);
    dim3 block(C4);
    ema_kernel<<<grid, block>>>(x, y);
}

// round 7
// speedup vs baseline: 1.2177x; 1.2177x over previous
#include <cuda_runtime.h>

// EMA over time: y_t = 0.1*y_{t-1} + 0.9*x_t, y_{-1} = 0.
// x [B=16, T=4000, C=512] fp32 -> y same shape.
//
// Decay is 10x per step: W-step warmup rebuilds carry to 0.1^W rel error,
// so T-chunks are independent -> fully parallel streaming kernel.
//
// R4 post-mortem: buying per-thread MLP with registers (regs 56) cost
// occupancy at a net DRAM% loss. Resident warps are the lever. R5: back to
// the 32-reg G=5 shape, CHUNK 25 -> 2560 CTAs (~16/SM, reg ceiling),
// W=4 (0.1^4 = 1e-4 rel on carry, ~2e-6 end-to-end; gate is 1e-3),
// __ldcs/__stcs streaming hints (data touched once).

static constexpr int B = 16;
static constexpr int T = 4000;
static constexpr int C = 512;
static constexpr int C4 = C / 4;        // 128 float4 lanes per (b,t) row
static constexpr int CHUNK = 25;        // 160 chunks along T -> 2560 CTAs
static constexpr int NCHUNK = T / CHUNK;
static constexpr int W = 4;             // warmup steps; 0.1^4 = 1e-4
static constexpr int G = 5;             // timesteps per inner group

__global__ __launch_bounds__(C4) void ema_kernel(const float4* __restrict__ x,
                                                 float4* __restrict__ y) {
    const int c4 = threadIdx.x;          // 0..127
    const int chunk = blockIdx.x;        // 0..159
    const int b = blockIdx.y;            // 0..15

    const float a = 0.9f;
    const float om = 0.1f;

    const int t0 = chunk * CHUNK;
    const size_t base = (size_t)b * T * C4 + c4;

    float4 acc = make_float4(0.f, 0.f, 0.f, 0.f);

    // Warmup: rebuild carry from up to W steps back (first chunk has none).
    if (t0 >= W) {
        size_t widx = base + (size_t)(t0 - W) * C4;
        float4 v[W];
        #pragma unroll
        for (int t = 0; t < W; ++t) v[t] = x[widx + (size_t)t * C4];
        #pragma unroll
        for (int t = 0; t < W; ++t) {
            acc.x = fmaf(om, acc.x, a * v[t].x);
            acc.y = fmaf(om, acc.y, a * v[t].y);
            acc.z = fmaf(om, acc.z, a * v[t].z);
            acc.w = fmaf(om, acc.w, a * v[t].w);
        }
    }

    // Main chunk: G-wide streaming load batches, FMA chain, streaming stores.
    size_t idx = base + (size_t)t0 * C4;
    for (int g = 0; g < CHUNK / G; ++g) {
        float4 v[G];
        #pragma unroll
        for (int t = 0; t < G; ++t) v[t] = __ldcs(&x[idx + (size_t)t * C4]);
        #pragma unroll
        for (int t = 0; t < G; ++t) {
            acc.x = fmaf(om, acc.x, a * v[t].x);
            acc.y = fmaf(om, acc.y, a * v[t].y);
            acc.z = fmaf(om, acc.z, a * v[t].z);
            acc.w = fmaf(om, acc.w, a * v[t].w);
            v[t] = acc;
        }
        #pragma unroll
        for (int t = 0; t < G; ++t)
            __stcs(&y[idx + (size_t)t * C4], v[t]);
        idx += (size_t)G * C4;
    }
}

extern "C" void kernel_launch(void* const* d_in, const int* in_sizes, int n_in,
                              void* d_out, int out_size) {
    const float4* x = (const float4*)d_in[0];
    float4* y = (float4*)d_out;
    dim3 grid(NCHUNK, B);
    dim3 block(C4);
    ema_kernel<<<grid, block>>>(x, y);
}